// round 1
// baseline (speedup 1.0000x reference)
#include <cuda_runtime.h>
#include <cuda_bf16.h>
#include <cstdint>

// Problem shape (fixed dataset): x [2,4096,4096] f32, weight [4096,4096] f32, bias [4096] f32
// M = 8192, K = 4096, N = 4096. Output f32 [2,4096,4096] (values passed through bf16).

#define MAX_M 8192
#define MAX_K 4096
#define MAX_N 4096

// Scratch (allocation-free rule: __device__ globals)
__device__ int8_t g_xi8[(size_t)MAX_M * MAX_K];
__device__ int8_t g_wi8[(size_t)MAX_N * MAX_K];
__device__ float  g_xs[MAX_M];
__device__ float  g_ws[MAX_N];

// ---------------------------------------------------------------------------
// Per-row symmetric int8 quantization: scale = max(absmax/127, 1e-12),
// q = clip(rint(v/scale), -128, 127). One block per row.
// ---------------------------------------------------------------------------
__global__ void quant_rows_kernel(const float* __restrict__ src,
                                  int8_t* __restrict__ dst,
                                  float* __restrict__ scales, int K) {
    const int row = blockIdx.x;
    const int nk4 = K >> 2;
    const float4* s4 = reinterpret_cast<const float4*>(src) + (size_t)row * nk4;
    char4* d4 = reinterpret_cast<char4*>(dst) + (size_t)row * nk4;

    float amax = 0.f;
    for (int i = threadIdx.x; i < nk4; i += blockDim.x) {
        float4 v = s4[i];
        amax = fmaxf(amax, fmaxf(fmaxf(fabsf(v.x), fabsf(v.y)),
                                 fmaxf(fabsf(v.z), fabsf(v.w))));
    }
    __shared__ float red[32];
    #pragma unroll
    for (int o = 16; o; o >>= 1) amax = fmaxf(amax, __shfl_xor_sync(0xffffffffu, amax, o));
    if ((threadIdx.x & 31) == 0) red[threadIdx.x >> 5] = amax;
    __syncthreads();
    if (threadIdx.x < 32) {
        float v = (threadIdx.x < (blockDim.x >> 5)) ? red[threadIdx.x] : 0.f;
        #pragma unroll
        for (int o = 16; o; o >>= 1) v = fmaxf(v, __shfl_xor_sync(0xffffffffu, v, o));
        if (threadIdx.x == 0) red[0] = fmaxf(v / 127.0f, 1e-12f);
    }
    __syncthreads();
    const float scale = red[0];
    if (threadIdx.x == 0) scales[row] = scale;

    for (int i = threadIdx.x; i < nk4; i += blockDim.x) {
        float4 v = s4[i];  // L1 hit (same row just read)
        char4 q;
        q.x = (signed char)(int)fminf(fmaxf(rintf(v.x / scale), -128.f), 127.f);
        q.y = (signed char)(int)fminf(fmaxf(rintf(v.y / scale), -128.f), 127.f);
        q.z = (signed char)(int)fminf(fmaxf(rintf(v.z / scale), -128.f), 127.f);
        q.w = (signed char)(int)fminf(fmaxf(rintf(v.w / scale), -128.f), 127.f);
        d4[i] = q;
    }
}

// ---------------------------------------------------------------------------
// int8 GEMM (NT: both operands K-contiguous) with mma.sync.m16n8k32.s8,
// fused dequant + bf16 rounding + bf16 bias add, fp32 store.
// Block tile 128x128, warp tile 64x32, BK=64. 8 warps.
// ---------------------------------------------------------------------------
#define BM 128
#define BN 128
#define BK 64
#define SSTRIDE 80   // padded shared row stride (bytes) -> conflict-free frag loads

__device__ __forceinline__ float finish_elem(int acc, float sx, float sw, float bias_bf) {
    float v = ((float)acc * sx) * sw;                 // matches acc * x_s * w_s order
    float o = __bfloat162float(__float2bfloat16(v));  // .astype(bf16)
    return __bfloat162float(__float2bfloat16(o + bias_bf)); // bf16 add, widen to f32
}

__global__ __launch_bounds__(256) void gemm_i8_kernel(
    const float* __restrict__ bias, float* __restrict__ out,
    int M, int N, int K) {
    __shared__ __align__(16) int8_t As[BM * SSTRIDE];
    __shared__ __align__(16) int8_t Bs[BN * SSTRIDE];

    const int tid = threadIdx.x;
    const int m0 = blockIdx.y * BM;
    const int n0 = blockIdx.x * BN;
    const int warp = tid >> 5, lane = tid & 31;
    const int wm = (warp & 1) * 64;   // warp M offset within block
    const int wn = (warp >> 1) * 32;  // warp N offset within block
    const int g = lane >> 2, tig = lane & 3;

    int acc[4][4][4];
    #pragma unroll
    for (int i = 0; i < 4; i++)
        #pragma unroll
        for (int j = 0; j < 4; j++)
            #pragma unroll
            for (int r = 0; r < 4; r++) acc[i][j][r] = 0;

    const int8_t* Aglob = g_xi8;
    const int8_t* Bglob = g_wi8;

    for (int kt = 0; kt < K; kt += BK) {
        // Load 128x64B tiles of A and B (512 int4 each, 256 threads x 2)
        #pragma unroll
        for (int p = 0; p < 2; p++) {
            int q = tid + p * 256;           // 0..511
            int row = q >> 2;
            int seg = (q & 3) * 16;
            *reinterpret_cast<int4*>(As + row * SSTRIDE + seg) =
                *reinterpret_cast<const int4*>(Aglob + (size_t)(m0 + row) * K + kt + seg);
            *reinterpret_cast<int4*>(Bs + row * SSTRIDE + seg) =
                *reinterpret_cast<const int4*>(Bglob + (size_t)(n0 + row) * K + kt + seg);
        }
        __syncthreads();

        #pragma unroll
        for (int ks = 0; ks < BK; ks += 32) {
            int a[4][4], b[4][2];
            #pragma unroll
            for (int i = 0; i < 4; i++) {
                #pragma unroll
                for (int r = 0; r < 4; r++) {
                    int row = wm + i * 16 + g + (r & 1) * 8;
                    int kb = ks + tig * 4 + (r >> 1) * 16;
                    a[i][r] = *reinterpret_cast<const int*>(As + row * SSTRIDE + kb);
                }
            }
            #pragma unroll
            for (int j = 0; j < 4; j++) {
                int col = wn + j * 8 + g;
                b[j][0] = *reinterpret_cast<const int*>(Bs + col * SSTRIDE + ks + tig * 4);
                b[j][1] = *reinterpret_cast<const int*>(Bs + col * SSTRIDE + ks + tig * 4 + 16);
            }
            #pragma unroll
            for (int i = 0; i < 4; i++) {
                #pragma unroll
                for (int j = 0; j < 4; j++) {
                    asm volatile(
                        "mma.sync.aligned.m16n8k32.row.col.s32.s8.s8.s32 "
                        "{%0,%1,%2,%3},{%4,%5,%6,%7},{%8,%9},{%0,%1,%2,%3};"
                        : "+r"(acc[i][j][0]), "+r"(acc[i][j][1]),
                          "+r"(acc[i][j][2]), "+r"(acc[i][j][3])
                        : "r"(a[i][0]), "r"(a[i][1]), "r"(a[i][2]), "r"(a[i][3]),
                          "r"(b[j][0]), "r"(b[j][1]));
                }
            }
        }
        __syncthreads();
    }

    // Epilogue: dequant + bf16 round + bf16 bias add -> f32
    #pragma unroll
    for (int i = 0; i < 4; i++) {
        int r0 = m0 + wm + i * 16 + g;
        float sx0 = g_xs[r0];
        float sx1 = g_xs[r0 + 8];
        #pragma unroll
        for (int j = 0; j < 4; j++) {
            int c0 = n0 + wn + j * 8 + 2 * tig;
            float sw0 = g_ws[c0], sw1 = g_ws[c0 + 1];
            float bb0 = __bfloat162float(__float2bfloat16(bias[c0]));
            float bb1 = __bfloat162float(__float2bfloat16(bias[c0 + 1]));
            out[(size_t)r0 * N + c0]           = finish_elem(acc[i][j][0], sx0, sw0, bb0);
            out[(size_t)r0 * N + c0 + 1]       = finish_elem(acc[i][j][1], sx0, sw1, bb1);
            out[(size_t)(r0 + 8) * N + c0]     = finish_elem(acc[i][j][2], sx1, sw0, bb0);
            out[(size_t)(r0 + 8) * N + c0 + 1] = finish_elem(acc[i][j][3], sx1, sw1, bb1);
        }
    }
}

// ---------------------------------------------------------------------------
extern "C" void kernel_launch(void* const* d_in, const int* in_sizes, int n_in,
                              void* d_out, int out_size) {
    const float* x      = (const float*)d_in[0];
    const float* weight = (const float*)d_in[1];
    const float* bias   = (const float*)d_in[2];
    float* out = (float*)d_out;

    const int N = in_sizes[2];
    const int K = in_sizes[1] / N;
    const int M = in_sizes[0] / K;

    // Quantize weights (N rows) and activations (M rows)
    {
        int8_t* wi8; cudaGetSymbolAddress((void**)&wi8, g_wi8);
        int8_t* xi8; cudaGetSymbolAddress((void**)&xi8, g_xi8);
        float* ws;   cudaGetSymbolAddress((void**)&ws, g_ws);
        float* xs;   cudaGetSymbolAddress((void**)&xs, g_xs);
        quant_rows_kernel<<<N, 256>>>(weight, wi8, ws, K);
        quant_rows_kernel<<<M, 256>>>(x, xi8, xs, K);
    }

    dim3 grid(N / BN, M / BM);
    gemm_i8_kernel<<<grid, 256>>>(bias, out, M, N, K);
}

// round 3
// speedup vs baseline: 1.0392x; 1.0392x over previous
#include <cuda_runtime.h>
#include <cuda_bf16.h>
#include <cstdint>

// x [2,4096,4096] f32, weight [4096,4096] f32, bias [4096] f32 -> out f32
// M=8192, K=4096, N=4096

#define MAX_M 8192
#define MAX_K 4096
#define MAX_N 4096

__device__ int8_t g_xi8[(size_t)MAX_M * MAX_K];
__device__ int8_t g_wi8[(size_t)MAX_N * MAX_K];
__device__ float  g_xs[MAX_M];
__device__ float  g_ws[MAX_N];

// ---------------------------------------------------------------------------
// Per-row symmetric int8 quantization
// ---------------------------------------------------------------------------
__global__ void quant_rows_kernel(const float* __restrict__ src,
                                  int8_t* __restrict__ dst,
                                  float* __restrict__ scales, int K) {
    const int row = blockIdx.x;
    const int nk4 = K >> 2;
    const float4* s4 = reinterpret_cast<const float4*>(src) + (size_t)row * nk4;
    char4* d4 = reinterpret_cast<char4*>(dst) + (size_t)row * nk4;

    float amax = 0.f;
    for (int i = threadIdx.x; i < nk4; i += blockDim.x) {
        float4 v = s4[i];
        amax = fmaxf(amax, fmaxf(fmaxf(fabsf(v.x), fabsf(v.y)),
                                 fmaxf(fabsf(v.z), fabsf(v.w))));
    }
    __shared__ float red[32];
    #pragma unroll
    for (int o = 16; o; o >>= 1) amax = fmaxf(amax, __shfl_xor_sync(0xffffffffu, amax, o));
    if ((threadIdx.x & 31) == 0) red[threadIdx.x >> 5] = amax;
    __syncthreads();
    if (threadIdx.x < 32) {
        float v = (threadIdx.x < (blockDim.x >> 5)) ? red[threadIdx.x] : 0.f;
        #pragma unroll
        for (int o = 16; o; o >>= 1) v = fmaxf(v, __shfl_xor_sync(0xffffffffu, v, o));
        if (threadIdx.x == 0) red[0] = fmaxf(v / 127.0f, 1e-12f);
    }
    __syncthreads();
    const float scale = red[0];
    if (threadIdx.x == 0) scales[row] = scale;

    for (int i = threadIdx.x; i < nk4; i += blockDim.x) {
        float4 v = s4[i];
        char4 q;
        q.x = (signed char)(int)fminf(fmaxf(rintf(v.x / scale), -128.f), 127.f);
        q.y = (signed char)(int)fminf(fmaxf(rintf(v.y / scale), -128.f), 127.f);
        q.z = (signed char)(int)fminf(fmaxf(rintf(v.z / scale), -128.f), 127.f);
        q.w = (signed char)(int)fminf(fmaxf(rintf(v.w / scale), -128.f), 127.f);
        d4[i] = q;
    }
}

// ---------------------------------------------------------------------------
// int8 GEMM: mma.sync.m16n8k32 + cp.async 4-stage pipeline + ldmatrix frags.
// Block 128x128, BK=64, 8 warps (2x4), warp tile 64x32.
// ---------------------------------------------------------------------------
#define BM 128
#define BN 128
#define BK 64
#define STAGES 4
#define ASTRIDE 80                       // 64B data + 16B pad: conflict-free
#define STAGE_BYTES (2 * BM * ASTRIDE)   // A tile + B tile per stage (20480)
#define SMEM_BYTES (STAGES * STAGE_BYTES)

__device__ __forceinline__ uint32_t smem_u32(const void* p) {
    uint32_t a;
    asm("{ .reg .u64 t; cvta.to.shared.u64 t, %1; cvt.u32.u64 %0, t; }" : "=r"(a) : "l"(p));
    return a;
}
__device__ __forceinline__ void cp_async16(uint32_t dst, const void* src) {
    asm volatile("cp.async.cg.shared.global [%0], [%1], 16;" :: "r"(dst), "l"(src));
}
__device__ __forceinline__ void cp_commit() {
    asm volatile("cp.async.commit_group;" ::: "memory");
}
template <int N>
__device__ __forceinline__ void cp_wait() {
    asm volatile("cp.async.wait_group %0;" :: "n"(N) : "memory");
}
__device__ __forceinline__ void ldsm_x4(int& r0, int& r1, int& r2, int& r3, uint32_t a) {
    asm volatile("ldmatrix.sync.aligned.m8n8.x4.shared.b16 {%0,%1,%2,%3}, [%4];"
                 : "=r"(r0), "=r"(r1), "=r"(r2), "=r"(r3) : "r"(a));
}

__device__ __forceinline__ float finish_elem(int acc, float sx, float sw, float bias_bf) {
    float v = ((float)acc * sx) * sw;
    float o = __bfloat162float(__float2bfloat16(v));
    return __bfloat162float(__float2bfloat16(o + bias_bf));
}

__global__ void __launch_bounds__(256, 1) gemm_i8_kernel(
    const float* __restrict__ bias, float* __restrict__ out,
    int M, int N, int K) {
    extern __shared__ char smem[];
    const uint32_t sb = smem_u32(smem);

    const int tid = threadIdx.x;
    const int warp = tid >> 5, lane = tid & 31;
    const int m0 = blockIdx.y * BM;
    const int n0 = blockIdx.x * BN;
    const int wm = (warp >> 2) * 64;   // 2 warps in M
    const int wn = (warp & 3) * 32;    // 4 warps in N
    const int g = lane >> 2, tig = lane & 3;

    const int8_t* Ag = g_xi8 + (size_t)m0 * K;
    const int8_t* Bg = g_wi8 + (size_t)n0 * K;

    // cp.async mapping: 512 16B segments per tile; thread handles 2 per tile.
    // seg q: row = q>>2, chunk = q&3 (4 consecutive lanes cover one 64B row).
    const int r_ld0 = tid >> 2, c_ld = (tid & 3) * 16;
    const int r_ld1 = (tid + 256) >> 2;

    // ldmatrix lane offsets (byte offsets inside a stage tile)
    uint32_t aoff[4], boff[2];
    #pragma unroll
    for (int i = 0; i < 4; i++)
        aoff[i] = (uint32_t)((wm + i * 16 + (lane & 15)) * ASTRIDE + ((lane >> 4) << 4));
    #pragma unroll
    for (int jj = 0; jj < 2; jj++)
        boff[jj] = (uint32_t)((wn + ((jj << 1) + ((lane >> 4) & 1)) * 8 + (lane & 7)) * ASTRIDE
                              + (((lane >> 3) & 1) << 4));

    int acc[4][4][4];
    #pragma unroll
    for (int i = 0; i < 4; i++)
        #pragma unroll
        for (int j = 0; j < 4; j++)
            #pragma unroll
            for (int r = 0; r < 4; r++) acc[i][j][r] = 0;

    const int nchunks = K / BK;

    auto issue_stage = [&](int c) {
        const int s = c % STAGES;
        const int kt = c * BK;
        const uint32_t ab = sb + s * STAGE_BYTES;
        const uint32_t bb = ab + BM * ASTRIDE;
        cp_async16(ab + r_ld0 * ASTRIDE + c_ld, Ag + (size_t)r_ld0 * K + kt + c_ld);
        cp_async16(ab + r_ld1 * ASTRIDE + c_ld, Ag + (size_t)r_ld1 * K + kt + c_ld);
        cp_async16(bb + r_ld0 * ASTRIDE + c_ld, Bg + (size_t)r_ld0 * K + kt + c_ld);
        cp_async16(bb + r_ld1 * ASTRIDE + c_ld, Bg + (size_t)r_ld1 * K + kt + c_ld);
        cp_commit();
    };

    #pragma unroll
    for (int c = 0; c < STAGES - 1; c++) issue_stage(c);

    for (int c = 0; c < nchunks; c++) {
        cp_wait<STAGES - 2>();
        __syncthreads();

        if (c + STAGES - 1 < nchunks) issue_stage(c + STAGES - 1);

        const int s = c % STAGES;
        const uint32_t ab = sb + s * STAGE_BYTES;
        const uint32_t bb = ab + BM * ASTRIDE;

        #pragma unroll
        for (int ks = 0; ks < BK; ks += 32) {
            int fa[4][4], fb[4][2];
            #pragma unroll
            for (int i = 0; i < 4; i++)
                ldsm_x4(fa[i][0], fa[i][1], fa[i][2], fa[i][3], ab + aoff[i] + ks);
            #pragma unroll
            for (int jj = 0; jj < 2; jj++)
                ldsm_x4(fb[2 * jj][0], fb[2 * jj][1], fb[2 * jj + 1][0], fb[2 * jj + 1][1],
                        bb + boff[jj] + ks);
            #pragma unroll
            for (int i = 0; i < 4; i++) {
                #pragma unroll
                for (int j = 0; j < 4; j++) {
                    asm volatile(
                        "mma.sync.aligned.m16n8k32.row.col.s32.s8.s8.s32 "
                        "{%0,%1,%2,%3},{%4,%5,%6,%7},{%8,%9},{%0,%1,%2,%3};"
                        : "+r"(acc[i][j][0]), "+r"(acc[i][j][1]),
                          "+r"(acc[i][j][2]), "+r"(acc[i][j][3])
                        : "r"(fa[i][0]), "r"(fa[i][1]), "r"(fa[i][2]), "r"(fa[i][3]),
                          "r"(fb[j][0]), "r"(fb[j][1]));
                }
            }
        }
        __syncthreads();
    }

    // Epilogue: dequant + bf16 round + bf16 bias add -> f32
    #pragma unroll
    for (int i = 0; i < 4; i++) {
        int r0 = m0 + wm + i * 16 + g;
        float sx0 = g_xs[r0];
        float sx1 = g_xs[r0 + 8];
        #pragma unroll
        for (int j = 0; j < 4; j++) {
            int c0 = n0 + wn + j * 8 + 2 * tig;
            float sw0 = g_ws[c0], sw1 = g_ws[c0 + 1];
            float bb0 = __bfloat162float(__float2bfloat16(bias[c0]));
            float bb1 = __bfloat162float(__float2bfloat16(bias[c0 + 1]));
            float2 o0, o1;
            o0.x = finish_elem(acc[i][j][0], sx0, sw0, bb0);
            o0.y = finish_elem(acc[i][j][1], sx0, sw1, bb1);
            o1.x = finish_elem(acc[i][j][2], sx1, sw0, bb0);
            o1.y = finish_elem(acc[i][j][3], sx1, sw1, bb1);
            *reinterpret_cast<float2*>(out + (size_t)r0 * N + c0) = o0;
            *reinterpret_cast<float2*>(out + (size_t)(r0 + 8) * N + c0) = o1;
        }
    }
}

// ---------------------------------------------------------------------------
extern "C" void kernel_launch(void* const* d_in, const int* in_sizes, int n_in,
                              void* d_out, int out_size) {
    const float* x      = (const float*)d_in[0];
    const float* weight = (const float*)d_in[1];
    const float* bias   = (const float*)d_in[2];
    float* out = (float*)d_out;

    const int N = in_sizes[2];
    const int K = in_sizes[1] / N;
    const int M = in_sizes[0] / K;

    int8_t* wi8; cudaGetSymbolAddress((void**)&wi8, g_wi8);
    int8_t* xi8; cudaGetSymbolAddress((void**)&xi8, g_xi8);
    float* ws;   cudaGetSymbolAddress((void**)&ws, g_ws);
    float* xs;   cudaGetSymbolAddress((void**)&xs, g_xs);
    quant_rows_kernel<<<N, 256>>>(weight, wi8, ws, K);
    quant_rows_kernel<<<M, 256>>>(x, xi8, xs, K);

    cudaFuncSetAttribute(gemm_i8_kernel, cudaFuncAttributeMaxDynamicSharedMemorySize, SMEM_BYTES);
    dim3 grid(N / BN, M / BM);
    gemm_i8_kernel<<<grid, 256, SMEM_BYTES>>>(bias, out, M, N, K);
}

// round 4
// speedup vs baseline: 1.0395x; 1.0003x over previous
#include <cuda_runtime.h>
#include <cuda_bf16.h>
#include <cstdint>

// x [2,4096,4096] f32, weight [4096,4096] f32, bias [4096] f32 -> out f32
// M=8192, K=4096, N=4096

#define MAX_M 8192
#define MAX_K 4096
#define MAX_N 4096

__device__ int8_t g_xi8[(size_t)MAX_M * MAX_K];
__device__ int8_t g_wi8[(size_t)MAX_N * MAX_K];
__device__ float  g_xs[MAX_M];
__device__ float  g_ws[MAX_N];

// ---------------------------------------------------------------------------
// Per-row symmetric int8 quantization
// ---------------------------------------------------------------------------
__global__ void quant_rows_kernel(const float* __restrict__ src,
                                  int8_t* __restrict__ dst,
                                  float* __restrict__ scales, int K) {
    const int row = blockIdx.x;
    const int nk4 = K >> 2;
    const float4* s4 = reinterpret_cast<const float4*>(src) + (size_t)row * nk4;
    char4* d4 = reinterpret_cast<char4*>(dst) + (size_t)row * nk4;

    float amax = 0.f;
    for (int i = threadIdx.x; i < nk4; i += blockDim.x) {
        float4 v = s4[i];
        amax = fmaxf(amax, fmaxf(fmaxf(fabsf(v.x), fabsf(v.y)),
                                 fmaxf(fabsf(v.z), fabsf(v.w))));
    }
    __shared__ float red[32];
    #pragma unroll
    for (int o = 16; o; o >>= 1) amax = fmaxf(amax, __shfl_xor_sync(0xffffffffu, amax, o));
    if ((threadIdx.x & 31) == 0) red[threadIdx.x >> 5] = amax;
    __syncthreads();
    if (threadIdx.x < 32) {
        float v = (threadIdx.x < (blockDim.x >> 5)) ? red[threadIdx.x] : 0.f;
        #pragma unroll
        for (int o = 16; o; o >>= 1) v = fmaxf(v, __shfl_xor_sync(0xffffffffu, v, o));
        if (threadIdx.x == 0) red[0] = fmaxf(v / 127.0f, 1e-12f);
    }
    __syncthreads();
    const float scale = red[0];
    if (threadIdx.x == 0) scales[row] = scale;

    for (int i = threadIdx.x; i < nk4; i += blockDim.x) {
        float4 v = s4[i];
        char4 q;
        q.x = (signed char)(int)fminf(fmaxf(rintf(v.x / scale), -128.f), 127.f);
        q.y = (signed char)(int)fminf(fmaxf(rintf(v.y / scale), -128.f), 127.f);
        q.z = (signed char)(int)fminf(fmaxf(rintf(v.z / scale), -128.f), 127.f);
        q.w = (signed char)(int)fminf(fmaxf(rintf(v.w / scale), -128.f), 127.f);
        d4[i] = q;
    }
}

// ---------------------------------------------------------------------------
// int8 GEMM: mma.sync.m16n8k32 + cp.async 4-stage pipeline + ldmatrix frags.
// Block 128x128, BK=64, 8 warps (2x4), warp tile 64x32.
// ---------------------------------------------------------------------------
#define BM 128
#define BN 128
#define BK 64
#define STAGES 4
#define ASTRIDE 80                       // 64B data + 16B pad: conflict-free
#define STAGE_BYTES (2 * BM * ASTRIDE)   // A tile + B tile per stage (20480)
#define SMEM_BYTES (STAGES * STAGE_BYTES)

__device__ __forceinline__ uint32_t smem_u32(const void* p) {
    uint32_t a;
    asm("{ .reg .u64 t; cvta.to.shared.u64 t, %1; cvt.u32.u64 %0, t; }" : "=r"(a) : "l"(p));
    return a;
}
__device__ __forceinline__ void cp_async16(uint32_t dst, const void* src) {
    asm volatile("cp.async.cg.shared.global [%0], [%1], 16;" :: "r"(dst), "l"(src));
}
__device__ __forceinline__ void cp_commit() {
    asm volatile("cp.async.commit_group;" ::: "memory");
}
template <int N>
__device__ __forceinline__ void cp_wait() {
    asm volatile("cp.async.wait_group %0;" :: "n"(N) : "memory");
}
__device__ __forceinline__ void ldsm_x4(int& r0, int& r1, int& r2, int& r3, uint32_t a) {
    asm volatile("ldmatrix.sync.aligned.m8n8.x4.shared.b16 {%0,%1,%2,%3}, [%4];"
                 : "=r"(r0), "=r"(r1), "=r"(r2), "=r"(r3) : "r"(a));
}

__device__ __forceinline__ float finish_elem(int acc, float sx, float sw, float bias_bf) {
    float v = ((float)acc * sx) * sw;
    float o = __bfloat162float(__float2bfloat16(v));
    return __bfloat162float(__float2bfloat16(o + bias_bf));
}

__global__ void __launch_bounds__(256, 1) gemm_i8_kernel(
    const float* __restrict__ bias, float* __restrict__ out,
    int M, int N, int K) {
    extern __shared__ char smem[];
    const uint32_t sb = smem_u32(smem);

    const int tid = threadIdx.x;
    const int warp = tid >> 5, lane = tid & 31;
    const int m0 = blockIdx.y * BM;
    const int n0 = blockIdx.x * BN;
    const int wm = (warp >> 2) * 64;   // 2 warps in M
    const int wn = (warp & 3) * 32;    // 4 warps in N
    const int g = lane >> 2, tig = lane & 3;

    const int8_t* Ag = g_xi8 + (size_t)m0 * K;
    const int8_t* Bg = g_wi8 + (size_t)n0 * K;

    // cp.async mapping: 512 16B segments per tile; thread handles 2 per tile.
    // seg q: row = q>>2, chunk = q&3 (4 consecutive lanes cover one 64B row).
    const int r_ld0 = tid >> 2, c_ld = (tid & 3) * 16;
    const int r_ld1 = (tid + 256) >> 2;

    // ldmatrix lane offsets (byte offsets inside a stage tile)
    uint32_t aoff[4], boff[2];
    #pragma unroll
    for (int i = 0; i < 4; i++)
        aoff[i] = (uint32_t)((wm + i * 16 + (lane & 15)) * ASTRIDE + ((lane >> 4) << 4));
    #pragma unroll
    for (int jj = 0; jj < 2; jj++)
        boff[jj] = (uint32_t)((wn + ((jj << 1) + ((lane >> 4) & 1)) * 8 + (lane & 7)) * ASTRIDE
                              + (((lane >> 3) & 1) << 4));

    int acc[4][4][4];
    #pragma unroll
    for (int i = 0; i < 4; i++)
        #pragma unroll
        for (int j = 0; j < 4; j++)
            #pragma unroll
            for (int r = 0; r < 4; r++) acc[i][j][r] = 0;

    const int nchunks = K / BK;

    auto issue_stage = [&](int c) {
        const int s = c % STAGES;
        const int kt = c * BK;
        const uint32_t ab = sb + s * STAGE_BYTES;
        const uint32_t bb = ab + BM * ASTRIDE;
        cp_async16(ab + r_ld0 * ASTRIDE + c_ld, Ag + (size_t)r_ld0 * K + kt + c_ld);
        cp_async16(ab + r_ld1 * ASTRIDE + c_ld, Ag + (size_t)r_ld1 * K + kt + c_ld);
        cp_async16(bb + r_ld0 * ASTRIDE + c_ld, Bg + (size_t)r_ld0 * K + kt + c_ld);
        cp_async16(bb + r_ld1 * ASTRIDE + c_ld, Bg + (size_t)r_ld1 * K + kt + c_ld);
        cp_commit();
    };

    #pragma unroll
    for (int c = 0; c < STAGES - 1; c++) issue_stage(c);

    for (int c = 0; c < nchunks; c++) {
        cp_wait<STAGES - 2>();
        __syncthreads();

        if (c + STAGES - 1 < nchunks) issue_stage(c + STAGES - 1);

        const int s = c % STAGES;
        const uint32_t ab = sb + s * STAGE_BYTES;
        const uint32_t bb = ab + BM * ASTRIDE;

        #pragma unroll
        for (int ks = 0; ks < BK; ks += 32) {
            int fa[4][4], fb[4][2];
            #pragma unroll
            for (int i = 0; i < 4; i++)
                ldsm_x4(fa[i][0], fa[i][1], fa[i][2], fa[i][3], ab + aoff[i] + ks);
            #pragma unroll
            for (int jj = 0; jj < 2; jj++)
                ldsm_x4(fb[2 * jj][0], fb[2 * jj][1], fb[2 * jj + 1][0], fb[2 * jj + 1][1],
                        bb + boff[jj] + ks);
            #pragma unroll
            for (int i = 0; i < 4; i++) {
                #pragma unroll
                for (int j = 0; j < 4; j++) {
                    asm volatile(
                        "mma.sync.aligned.m16n8k32.row.col.s32.s8.s8.s32 "
                        "{%0,%1,%2,%3},{%4,%5,%6,%7},{%8,%9},{%0,%1,%2,%3};"
                        : "+r"(acc[i][j][0]), "+r"(acc[i][j][1]),
                          "+r"(acc[i][j][2]), "+r"(acc[i][j][3])
                        : "r"(fa[i][0]), "r"(fa[i][1]), "r"(fa[i][2]), "r"(fa[i][3]),
                          "r"(fb[j][0]), "r"(fb[j][1]));
                }
            }
        }
        __syncthreads();
    }

    // Epilogue: dequant + bf16 round + bf16 bias add -> f32
    #pragma unroll
    for (int i = 0; i < 4; i++) {
        int r0 = m0 + wm + i * 16 + g;
        float sx0 = g_xs[r0];
        float sx1 = g_xs[r0 + 8];
        #pragma unroll
        for (int j = 0; j < 4; j++) {
            int c0 = n0 + wn + j * 8 + 2 * tig;
            float sw0 = g_ws[c0], sw1 = g_ws[c0 + 1];
            float bb0 = __bfloat162float(__float2bfloat16(bias[c0]));
            float bb1 = __bfloat162float(__float2bfloat16(bias[c0 + 1]));
            float2 o0, o1;
            o0.x = finish_elem(acc[i][j][0], sx0, sw0, bb0);
            o0.y = finish_elem(acc[i][j][1], sx0, sw1, bb1);
            o1.x = finish_elem(acc[i][j][2], sx1, sw0, bb0);
            o1.y = finish_elem(acc[i][j][3], sx1, sw1, bb1);
            *reinterpret_cast<float2*>(out + (size_t)r0 * N + c0) = o0;
            *reinterpret_cast<float2*>(out + (size_t)(r0 + 8) * N + c0) = o1;
        }
    }
}

// ---------------------------------------------------------------------------
extern "C" void kernel_launch(void* const* d_in, const int* in_sizes, int n_in,
                              void* d_out, int out_size) {
    const float* x      = (const float*)d_in[0];
    const float* weight = (const float*)d_in[1];
    const float* bias   = (const float*)d_in[2];
    float* out = (float*)d_out;

    const int N = in_sizes[2];
    const int K = in_sizes[1] / N;
    const int M = in_sizes[0] / K;

    int8_t* wi8; cudaGetSymbolAddress((void**)&wi8, g_wi8);
    int8_t* xi8; cudaGetSymbolAddress((void**)&xi8, g_xi8);
    float* ws;   cudaGetSymbolAddress((void**)&ws, g_ws);
    float* xs;   cudaGetSymbolAddress((void**)&xs, g_xs);
    quant_rows_kernel<<<N, 256>>>(weight, wi8, ws, K);
    quant_rows_kernel<<<M, 256>>>(x, xi8, xs, K);

    cudaFuncSetAttribute(gemm_i8_kernel, cudaFuncAttributeMaxDynamicSharedMemorySize, SMEM_BYTES);
    dim3 grid(N / BN, M / BM);
    gemm_i8_kernel<<<grid, 256, SMEM_BYTES>>>(bias, out, M, N, K);
}